// round 2
// baseline (speedup 1.0000x reference)
#include <cuda_runtime.h>
#include <cstdint>

#define DIN   128
#define DOUT  128
#define TILE_M 128
#define THREADS 256
#define ROWPAD 132          // floats per x-row in smem (132 % 32 = 4 -> bank spread)
#define NK2    64           // 128 k / 2 (k-paired)
#define REDSTR 20           // reduction row stride (floats)

// ---- smem layout (dynamic) ----
#define SX_ELEMS   (TILE_M * ROWPAD)
#define SW2_U64    (NK2 * 128)
#define SMEM_BYTES (2*SX_ELEMS*4 + SW2_U64*8 + 2*128*REDSTR*4 + (128*4 + 1)*4)

__device__ __forceinline__ unsigned smem_u32(const void* p) {
    return (unsigned)__cvta_generic_to_shared(p);
}
__device__ __forceinline__ void cp_async16(unsigned dst, const void* src) {
    asm volatile("cp.async.ca.shared.global [%0], [%1], 16;\n" :: "r"(dst), "l"(src));
}
__device__ __forceinline__ void cp_commit() { asm volatile("cp.async.commit_group;\n"); }
__device__ __forceinline__ void cp_wait0()  { asm volatile("cp.async.wait_group 0;\n"); }

// Blackwell packed fp32x2 FMA: lo/hi lanes accumulate even/odd-k partial sums.
__device__ __forceinline__ unsigned long long ffma2(unsigned long long a,
                                                    unsigned long long b,
                                                    unsigned long long c) {
    unsigned long long d;
    asm("fma.rn.f32x2 %0, %1, %2, %3;" : "=l"(d) : "l"(a), "l"(b), "l"(c));
    return d;
}

extern "C" __global__ void __launch_bounds__(THREADS, 1)
mobius_linear_kernel(const float* __restrict__ X,
                     const float* __restrict__ W,
                     const float* __restrict__ bias,
                     float* __restrict__ out,
                     int nrows)
{
    extern __shared__ char smem_raw[];
    float* sX0 = (float*)smem_raw;
    float* sX1 = sX0 + SX_ELEMS;
    unsigned long long* sw2 = (unsigned long long*)(sX1 + SX_ELEMS);
    float* redA  = (float*)(sw2 + SW2_U64);
    float* redB  = redA + 128 * REDSTR;
    float* xn2s  = redB + 128 * REDSTR;
    float* coefA = xn2s + 128;
    float* coefB = coefA + 128;
    float* sbias = coefB + 128;
    float* sb2   = sbias + 128;

    const int tid = threadIdx.x;
    const int tx  = tid & 15;   // output-col group: cols tx*8 .. tx*8+7
    const int ty  = tid >> 4;   // row base: rows ty + 16*i, i=0..7

    if (tid < 128) sbias[tid] = bias[tid];

    // ---- Build sw2 once: u64 = (W[j][2k2], W[j][2k2+1]) at slot-permuted position.
    // Logical 16B-slot s (cols {2s,2s+1}) -> physical slot phi(s)=((s&3)<<4)|(s>>2)
    // so reader lanes (tx) hit consecutive 16B slots -> conflict-free LDS.128.
    #pragma unroll
    for (int i = 0; i < 32; i++) {
        int id = tid + THREADS * i;          // 0..8191 over (k2, phys u64 p)
        int k2 = id >> 7;
        int p  = id & 127;                   // physical u64 index within row
        int phs = p >> 1;                    // physical 16B slot
        int s   = (phs >> 4) + ((phs & 15) << 2);  // inverse permutation
        int j   = 2 * s + (p & 1);           // logical output column
        float2 w = *(const float2*)(W + j * DIN + 2 * k2);
        unsigned long long v = (unsigned long long)__float_as_uint(w.x)
                             | ((unsigned long long)__float_as_uint(w.y) << 32);
        sw2[k2 * 128 + p] = v;
    }
    __syncthreads();

    // ---- b2 = ||bias||^2 (once)
    if (tid < 32) {
        float s = 0.f;
        #pragma unroll
        for (int i = 0; i < 4; i++) { float v = sbias[tid + 32 * i]; s = fmaf(v, v, s); }
        #pragma unroll
        for (int o = 16; o; o >>= 1) s += __shfl_xor_sync(0xffffffffu, s, o);
        if (tid == 0) *sb2 = s;
    }
    __syncthreads();

    const int ntiles = nrows / TILE_M;
    int tile = blockIdx.x;

    // ---- prefetch first tile into buf0 (4096 float4s, 16 per thread)
    if (tile < ntiles) {
        const float* src = X + (long long)tile * TILE_M * DIN;
        #pragma unroll
        for (int i = 0; i < 16; i++) {
            int f = tid + THREADS * i;
            int b = f >> 5, k4 = f & 31;
            cp_async16(smem_u32(sX0 + b * ROWPAD + k4 * 4), src + b * DIN + k4 * 4);
        }
    }
    cp_commit();

    int buf = 0;
    for (; tile < ntiles; tile += gridDim.x) {
        float* cur = buf ? sX1 : sX0;
        float* nxt = buf ? sX0 : sX1;

        cp_wait0();
        __syncthreads();   // cur ready; prior iter fully done -> safe to refill nxt

        // ---- prefetch next tile
        int tnext = tile + gridDim.x;
        if (tnext < ntiles) {
            const float* src = X + (long long)tnext * TILE_M * DIN;
            #pragma unroll
            for (int i = 0; i < 16; i++) {
                int f = tid + THREADS * i;
                int b = f >> 5, k4 = f & 31;
                cp_async16(smem_u32(nxt + b * ROWPAD + k4 * 4), src + b * DIN + k4 * 4);
            }
        }
        cp_commit();

        // ---- x_norm^2 per row: 2 lanes/row, float4 strided
        {
            int r = tid >> 1, q = tid & 1;
            const float4* row = (const float4*)(cur + r * ROWPAD) + q * 16;
            float s = 0.f;
            #pragma unroll
            for (int kk = 0; kk < 16; kk++) {
                float4 v = row[kk];
                s = fmaf(v.x, v.x, s); s = fmaf(v.y, v.y, s);
                s = fmaf(v.z, v.z, s); s = fmaf(v.w, v.w, s);
            }
            s += __shfl_xor_sync(0xffffffffu, s, 1);
            if (q == 0) xn2s[r] = s;
        }

        // ---- GEMM: 8x8 microtile (rows ty+16i), k-paired f32x2 accumulators
        unsigned long long acc[8][8];
        #pragma unroll
        for (int i = 0; i < 8; i++)
            #pragma unroll
            for (int j = 0; j < 8; j++) acc[i][j] = 0ULL;

        const float* abase = cur + ty * ROWPAD;
        const unsigned long long* brow = sw2 + ((unsigned)tx << 1);
        #pragma unroll 2
        for (int k2 = 0; k2 < NK2; k2++) {
            unsigned long long a2[8], b2v[8];
            #pragma unroll
            for (int i = 0; i < 8; i++)
                a2[i] = *(const unsigned long long*)(abase + i * 16 * ROWPAD + 2 * k2);
            #pragma unroll
            for (int jp = 0; jp < 4; jp++) {
                ulonglong2 t = *(const ulonglong2*)(brow + k2 * 128 + (jp << 5));
                b2v[2 * jp]     = t.x;
                b2v[2 * jp + 1] = t.y;
            }
            #pragma unroll
            for (int i = 0; i < 8; i++)
                #pragma unroll
                for (int j = 0; j < 8; j++)
                    acc[i][j] = ffma2(a2[i], b2v[j], acc[i][j]);
        }

        // ---- finish Mx (lo+hi), local reductions over this thread's 8 cols
        float bb[8];
        #pragma unroll
        for (int j = 0; j < 8; j++) bb[j] = sbias[tx * 8 + j];

        float m[8][8];
        #pragma unroll
        for (int i = 0; i < 8; i++) {
            float s2 = 0.f, sb = 0.f;
            #pragma unroll
            for (int j = 0; j < 8; j++) {
                float lo = __uint_as_float((unsigned)acc[i][j]);
                float hi = __uint_as_float((unsigned)(acc[i][j] >> 32));
                float v = lo + hi;
                m[i][j] = v;
                s2 = fmaf(v, v, s2);
                sb = fmaf(v, bb[j], sb);
            }
            int r = ty + 16 * i;
            redA[r * REDSTR + tx] = s2;
            redB[r * REDSTR + tx] = sb;
        }
        __syncthreads();

        // ---- per-row scalar math -> out = A*Mx + B*bias (mobius_add + projx folded)
        if (tid < 128) {
            int r = tid;
            const float4* pa = (const float4*)(redA + r * REDSTR);
            const float4* pb = (const float4*)(redB + r * REDSTR);
            float mxn2 = 0.f, dotb = 0.f;
            #pragma unroll
            for (int i = 0; i < 4; i++) {
                float4 a = pa[i]; mxn2 += (a.x + a.y) + (a.z + a.w);
                float4 b = pb[i]; dotb += (b.x + b.y) + (b.z + b.w);
            }
            float b2c = *sb2;
            float xn  = fmaxf(sqrtf(xn2s[r]), 1e-15f);
            float mxn = fmaxf(sqrtf(mxn2),   1e-15f);
            float u   = fminf(xn, 1.0f - 1e-7f);
            float at  = 0.5f * (log1pf(u) - log1pf(-u));
            float s   = tanhf(mxn / xn * at) / mxn;
            if (mxn <= 1e-10f) s = 0.0f;
            float xy    = s * dotb;                 // <y, bias>
            float y2    = s * s * mxn2;             // ||y||^2
            float alpha = 1.0f + 2.0f * xy + b2c;
            float beta  = 1.0f - y2;
            float den   = fmaxf(1.0f + 2.0f * xy + y2 * b2c, 1e-15f);
            float A  = s * alpha / den;
            float Bc = beta / den;
            float o2 = A * A * mxn2 + 2.0f * A * Bc * dotb + Bc * Bc * b2c;
            float on = fmaxf(sqrtf(o2), 1e-15f);
            float mx = 1.0f - 1e-5f;
            float f  = (on > mx) ? (mx / on) : 1.0f;
            coefA[r] = A * f;
            coefB[r] = Bc * f;
        }
        __syncthreads();

        // ---- write outputs (coalesced float4)
        float* orow = out + (long long)tile * TILE_M * DOUT;
        #pragma unroll
        for (int i = 0; i < 8; i++) {
            int r = ty + 16 * i;
            float A = coefA[r], Bc = coefB[r];
            float4 v0, v1;
            v0.x = fmaf(A, m[i][0], Bc * bb[0]);
            v0.y = fmaf(A, m[i][1], Bc * bb[1]);
            v0.z = fmaf(A, m[i][2], Bc * bb[2]);
            v0.w = fmaf(A, m[i][3], Bc * bb[3]);
            v1.x = fmaf(A, m[i][4], Bc * bb[4]);
            v1.y = fmaf(A, m[i][5], Bc * bb[5]);
            v1.z = fmaf(A, m[i][6], Bc * bb[6]);
            v1.w = fmaf(A, m[i][7], Bc * bb[7]);
            *(float4*)(orow + r * DOUT + tx * 8)     = v0;
            *(float4*)(orow + r * DOUT + tx * 8 + 4) = v1;
        }

        buf ^= 1;
    }
}

extern "C" void kernel_launch(void* const* d_in, const int* in_sizes, int n_in,
                              void* d_out, int out_size) {
    const float* X    = (const float*)d_in[0];
    const float* W    = (const float*)d_in[1];
    const float* bias = (const float*)d_in[2];
    float* out = (float*)d_out;

    int nrows = in_sizes[0] / DIN;

    cudaFuncSetAttribute(mobius_linear_kernel,
                         cudaFuncAttributeMaxDynamicSharedMemorySize, SMEM_BYTES);

    int nsm = 148;
    cudaDeviceGetAttribute(&nsm, cudaDevAttrMultiProcessorCount, 0);
    int ntiles = nrows / TILE_M;
    int grid = nsm < ntiles ? nsm : ntiles;

    mobius_linear_kernel<<<grid, THREADS, SMEM_BYTES>>>(X, W, bias, out, nrows);
}

// round 4
// speedup vs baseline: 2.0784x; 2.0784x over previous
#include <cuda_runtime.h>
#include <cstdint>

#define DIN    128
#define DOUT   128
#define TILE_M 128
#define THREADS 256
#define SPAD   132   // floats per staged x-row (132%32=4 -> spread banks)

// ---- smem byte offsets ----
#define OFF_STAGE 0
#define STAGE_BYTES (TILE_M*SPAD*4)            // 67584
#define OFF_AH   (OFF_STAGE + STAGE_BYTES)     // 8m x 8k frags * 512B = 32KB
#define OFF_AL   (OFF_AH + 32768)
#define OFF_WH   (OFF_AL + 32768)              // 8k x 16n frags * 256B = 32KB
#define OFF_WL   (OFF_WH + 32768)
#define OFF_BIAS (OFF_WL + 32768)
#define OFF_XN2  (OFF_BIAS + 512)
#define OFF_RS2  (OFF_XN2 + 512)               // [128][4] f32
#define OFF_RSB  (OFF_RS2 + 2048)
#define OFF_CA   (OFF_RSB + 2048)
#define OFF_CB   (OFF_CA + 512)
#define OFF_B2   (OFF_CB + 512)
#define SMEM_TOTAL (OFF_B2 + 16)

__device__ __forceinline__ unsigned smem_u32(const void* p) {
    return (unsigned)__cvta_generic_to_shared(p);
}
__device__ __forceinline__ void cp_async16(unsigned dst, const void* src) {
    asm volatile("cp.async.ca.shared.global [%0], [%1], 16;\n" :: "r"(dst), "l"(src));
}
__device__ __forceinline__ void cp_commit() { asm volatile("cp.async.commit_group;\n"); }
__device__ __forceinline__ void cp_wait0()  { asm volatile("cp.async.wait_group 0;\n"); }

// pack two f32 -> bf16x2 (hi arg -> upper 16 bits)
__device__ __forceinline__ uint32_t packbf(float hi, float lo) {
    uint32_t r; asm("cvt.rn.bf16x2.f32 %0, %1, %2;" : "=r"(r) : "f"(hi), "f"(lo)); return r;
}
__device__ __forceinline__ float lo_bf(uint32_t p) { return __uint_as_float(p << 16); }
__device__ __forceinline__ float hi_bf(uint32_t p) { return __uint_as_float(p & 0xffff0000u); }

__device__ __forceinline__ void mma_bf16(float4& d, const uint4& a, const uint2& b) {
    asm volatile("mma.sync.aligned.m16n8k16.row.col.f32.bf16.bf16.f32 "
        "{%0,%1,%2,%3}, {%4,%5,%6,%7}, {%8,%9}, {%0,%1,%2,%3};"
        : "+f"(d.x), "+f"(d.y), "+f"(d.z), "+f"(d.w)
        : "r"(a.x), "r"(a.y), "r"(a.z), "r"(a.w), "r"(b.x), "r"(b.y));
}

extern "C" __global__ void __launch_bounds__(THREADS, 1)
mobius_mma_kernel(const float* __restrict__ X,
                  const float* __restrict__ W,
                  const float* __restrict__ bias,
                  float* __restrict__ out,
                  int nrows)
{
    extern __shared__ __align__(16) char smem[];
    const uint32_t sbase = smem_u32(smem);
    float* stage = (float*)(smem + OFF_STAGE);
    float* sbias = (float*)(smem + OFF_BIAS);
    float* xn2s  = (float*)(smem + OFF_XN2);
    float* rs2   = (float*)(smem + OFF_RS2);
    float* rsb   = (float*)(smem + OFF_RSB);
    float* cA    = (float*)(smem + OFF_CA);
    float* cB    = (float*)(smem + OFF_CB);
    float* sB2   = (float*)(smem + OFF_B2);

    const int tid  = threadIdx.x;
    const int lane = tid & 31;
    const int wid  = tid >> 5;        // 8 warps
    const int g    = lane >> 2;       // group id (row within frag)
    const int cg   = lane & 3;        // thread-in-group (k/n pairs)
    const int wm   = wid >> 2;        // 0..1 : m-half (64 rows)
    const int wn   = wid & 3;         // 0..3 : n-quarter (32 cols)

    const int ntiles = nrows / TILE_M;
    const int t0 = blockIdx.x;

    // ---- prefetch first X tile ----
    if (t0 < ntiles) {
        const float* src = X + (long long)t0 * TILE_M * DIN;
        #pragma unroll
        for (int i = 0; i < 16; i++) {
            int f = tid + THREADS * i;           // 4096 float4s
            int b = f >> 5, k4 = f & 31;
            cp_async16(sbase + OFF_STAGE + (b * SPAD + k4 * 4) * 4,
                       src + b * DIN + k4 * 4);
        }
    }
    cp_commit();

    if (tid < 128) sbias[tid] = bias[tid];

    // ---- W conversion (once): warp wid = kstep, 16 ntiles each ----
    {
        const float* wp0 = W + (long long)wid * 16 + 2 * cg;
        #pragma unroll
        for (int nt = 0; nt < 16; nt++) {
            int n = nt * 8 + g;
            const float* wp = wp0 + n * DIN;
            float2 u0 = *(const float2*)(wp);
            float2 u1 = *(const float2*)(wp + 8);
            uint32_t h0 = packbf(u0.y, u0.x);
            uint32_t h1 = packbf(u1.y, u1.x);
            uint32_t l0 = packbf(u0.y - hi_bf(h0), u0.x - lo_bf(h0));
            uint32_t l1 = packbf(u1.y - hi_bf(h1), u1.x - lo_bf(h1));
            uint2 vh; vh.x = h0; vh.y = h1;
            uint2 vl; vl.x = l0; vl.y = l1;
            *(uint2*)(smem + OFF_WH + ((wid * 16 + nt) * 32 + lane) * 8) = vh;
            *(uint2*)(smem + OFF_WL + ((wid * 16 + nt) * 32 + lane) * 8) = vl;
        }
    }
    __syncthreads();

    // ---- b2 = ||bias||^2 ----
    if (tid < 32) {
        float s = 0.f;
        #pragma unroll
        for (int i = 0; i < 4; i++) { float v = sbias[tid + 32 * i]; s = fmaf(v, v, s); }
        #pragma unroll
        for (int o = 16; o; o >>= 1) s += __shfl_xor_sync(0xffffffffu, s, o);
        if (tid == 0) *sB2 = s;
    }

    // per-warp bias fragment values (cols wn*32 + j*8 + 2cg + {0,1})
    float2 bj[4];
    #pragma unroll
    for (int j = 0; j < 4; j++)
        bj[j] = *(const float2*)(sbias + wn * 32 + j * 8 + 2 * cg);

    for (int t = t0; t < ntiles; t += gridDim.x) {
        cp_wait0();
        __syncthreads();    // stage(t) ready; frag arrays free (prev mainloop done)

        // ---- A conversion: warp wid = mtile; write AH/AL frags + xn2 ----
        {
            const float* r0p = stage + (wid * 16 + g) * SPAD + 2 * cg;
            const float* r1p = r0p + 8 * SPAD;
            float xa0 = 0.f, xa1 = 0.f;
            #pragma unroll
            for (int s = 0; s < 8; s++) {
                float2 v00 = *(const float2*)(r0p + s * 16);
                float2 v01 = *(const float2*)(r0p + s * 16 + 8);
                float2 v10 = *(const float2*)(r1p + s * 16);
                float2 v11 = *(const float2*)(r1p + s * 16 + 8);
                xa0 = fmaf(v00.x, v00.x, xa0); xa0 = fmaf(v00.y, v00.y, xa0);
                xa0 = fmaf(v01.x, v01.x, xa0); xa0 = fmaf(v01.y, v01.y, xa0);
                xa1 = fmaf(v10.x, v10.x, xa1); xa1 = fmaf(v10.y, v10.y, xa1);
                xa1 = fmaf(v11.x, v11.x, xa1); xa1 = fmaf(v11.y, v11.y, xa1);
                uint4 h, l;
                h.x = packbf(v00.y, v00.x);
                h.y = packbf(v10.y, v10.x);
                h.z = packbf(v01.y, v01.x);
                h.w = packbf(v11.y, v11.x);
                l.x = packbf(v00.y - hi_bf(h.x), v00.x - lo_bf(h.x));
                l.y = packbf(v10.y - hi_bf(h.y), v10.x - lo_bf(h.y));
                l.z = packbf(v01.y - hi_bf(h.z), v01.x - lo_bf(h.z));
                l.w = packbf(v11.y - hi_bf(h.w), v11.x - lo_bf(h.w));
                *(uint4*)(smem + OFF_AH + ((wid * 8 + s) * 32 + lane) * 16) = h;
                *(uint4*)(smem + OFF_AL + ((wid * 8 + s) * 32 + lane) * 16) = l;
            }
            xa0 += __shfl_xor_sync(0xffffffffu, xa0, 1);
            xa0 += __shfl_xor_sync(0xffffffffu, xa0, 2);
            xa1 += __shfl_xor_sync(0xffffffffu, xa1, 1);
            xa1 += __shfl_xor_sync(0xffffffffu, xa1, 2);
            if (cg == 0) {
                xn2s[wid * 16 + g]     = xa0;
                xn2s[wid * 16 + g + 8] = xa1;
            }
        }
        __syncthreads();    // frags visible; stage reads complete

        // ---- prefetch next tile (stage now free) ----
        int tn = t + gridDim.x;
        if (tn < ntiles) {
            const float* src = X + (long long)tn * TILE_M * DIN;
            #pragma unroll
            for (int i = 0; i < 16; i++) {
                int f = tid + THREADS * i;
                int b = f >> 5, k4 = f & 31;
                cp_async16(sbase + OFF_STAGE + (b * SPAD + k4 * 4) * 4,
                           src + b * DIN + k4 * 4);
            }
        }
        cp_commit();

        // ---- mainloop: warp tile m64 x n32, 3-pass bf16 ----
        float4 acc[4][4];
        #pragma unroll
        for (int i = 0; i < 4; i++)
            #pragma unroll
            for (int j = 0; j < 4; j++) acc[i][j] = make_float4(0.f, 0.f, 0.f, 0.f);

        #pragma unroll
        for (int s = 0; s < 8; s++) {
            uint4 ah[4];
            uint2 wh[4];
            #pragma unroll
            for (int i = 0; i < 4; i++)
                ah[i] = *(const uint4*)(smem + OFF_AH + (((wm * 4 + i) * 8 + s) * 32 + lane) * 16);
            #pragma unroll
            for (int j = 0; j < 4; j++)
                wh[j] = *(const uint2*)(smem + OFF_WH + ((s * 16 + wn * 4 + j) * 32 + lane) * 8);
            #pragma unroll
            for (int i = 0; i < 4; i++)
                #pragma unroll
                for (int j = 0; j < 4; j++)
                    mma_bf16(acc[i][j], ah[i], wh[j]);
            uint4 al[4];
            #pragma unroll
            for (int i = 0; i < 4; i++)
                al[i] = *(const uint4*)(smem + OFF_AL + (((wm * 4 + i) * 8 + s) * 32 + lane) * 16);
            #pragma unroll
            for (int i = 0; i < 4; i++)
                #pragma unroll
                for (int j = 0; j < 4; j++)
                    mma_bf16(acc[i][j], al[i], wh[j]);
            uint2 wl[4];
            #pragma unroll
            for (int j = 0; j < 4; j++)
                wl[j] = *(const uint2*)(smem + OFF_WL + ((s * 16 + wn * 4 + j) * 32 + lane) * 8);
            #pragma unroll
            for (int i = 0; i < 4; i++)
                #pragma unroll
                for (int j = 0; j < 4; j++)
                    mma_bf16(acc[i][j], ah[i], wl[j]);
        }

        // ---- epilogue reductions: Mx^2 and Mx.bias per row ----
        #pragma unroll
        for (int i = 0; i < 4; i++) {
            float s2a = 0.f, s2b = 0.f, sba = 0.f, sbb = 0.f;
            #pragma unroll
            for (int j = 0; j < 4; j++) {
                float4 d = acc[i][j];
                s2a = fmaf(d.x, d.x, s2a); s2a = fmaf(d.y, d.y, s2a);
                s2b = fmaf(d.z, d.z, s2b); s2b = fmaf(d.w, d.w, s2b);
                sba = fmaf(d.x, bj[j].x, sba); sba = fmaf(d.y, bj[j].y, sba);
                sbb = fmaf(d.z, bj[j].x, sbb); sbb = fmaf(d.w, bj[j].y, sbb);
            }
            s2a += __shfl_xor_sync(0xffffffffu, s2a, 1);
            s2a += __shfl_xor_sync(0xffffffffu, s2a, 2);
            s2b += __shfl_xor_sync(0xffffffffu, s2b, 1);
            s2b += __shfl_xor_sync(0xffffffffu, s2b, 2);
            sba += __shfl_xor_sync(0xffffffffu, sba, 1);
            sba += __shfl_xor_sync(0xffffffffu, sba, 2);
            sbb += __shfl_xor_sync(0xffffffffu, sbb, 1);
            sbb += __shfl_xor_sync(0xffffffffu, sbb, 2);
            if (cg == 0) {
                int r0 = wm * 64 + i * 16 + g;
                rs2[r0 * 4 + wn]       = s2a;
                rs2[(r0 + 8) * 4 + wn] = s2b;
                rsb[r0 * 4 + wn]       = sba;
                rsb[(r0 + 8) * 4 + wn] = sbb;
            }
        }
        __syncthreads();

        // ---- per-row scalar math (mobius_matvec scale + mobius_add + projx) ----
        if (tid < 128) {
            int r = tid;
            float4 a4 = *(const float4*)(rs2 + r * 4);
            float4 b4 = *(const float4*)(rsb + r * 4);
            float mxn2 = (a4.x + a4.y) + (a4.z + a4.w);
            float dotb = (b4.x + b4.y) + (b4.z + b4.w);
            float b2c = *sB2;
            float xn  = fmaxf(sqrtf(xn2s[r]), 1e-15f);
            float mxn = fmaxf(sqrtf(mxn2),   1e-15f);
            float u   = fminf(xn, 1.0f - 1e-7f);
            float at  = 0.5f * (log1pf(u) - log1pf(-u));
            float sc  = tanhf(mxn / xn * at) / mxn;
            if (mxn <= 1e-10f) sc = 0.0f;
            float xy    = sc * dotb;
            float y2    = sc * sc * mxn2;
            float alpha = 1.0f + 2.0f * xy + b2c;
            float beta  = 1.0f - y2;
            float den   = fmaxf(1.0f + 2.0f * xy + y2 * b2c, 1e-15f);
            float A  = sc * alpha / den;
            float Bc = beta / den;
            float o2 = A * A * mxn2 + 2.0f * A * Bc * dotb + Bc * Bc * b2c;
            float on = fmaxf(sqrtf(o2), 1e-15f);
            float mxv = 1.0f - 1e-5f;
            float fpr = (on > mxv) ? (mxv / on) : 1.0f;
            cA[r] = A * fpr;
            cB[r] = Bc * fpr;
        }
        __syncthreads();

        // ---- stores: out = A[r]*Mx + B[r]*bias, straight from acc regs ----
        {
            float* obase = out + ((long long)t * TILE_M) * DOUT + wn * 32 + 2 * cg;
            #pragma unroll
            for (int i = 0; i < 4; i++) {
                int r0 = wm * 64 + i * 16 + g;
                float A0 = cA[r0],     B0 = cB[r0];
                float A1 = cA[r0 + 8], B1 = cB[r0 + 8];
                float* op0 = obase + (long long)r0 * DOUT;
                float* op1 = op0 + 8 * DOUT;
                #pragma unroll
                for (int j = 0; j < 4; j++) {
                    float4 d = acc[i][j];
                    float2 o0, o1;
                    o0.x = fmaf(A0, d.x, B0 * bj[j].x);
                    o0.y = fmaf(A0, d.y, B0 * bj[j].y);
                    o1.x = fmaf(A1, d.z, B1 * bj[j].x);
                    o1.y = fmaf(A1, d.w, B1 * bj[j].y);
                    *(float2*)(op0 + j * 8) = o0;
                    *(float2*)(op1 + j * 8) = o1;
                }
            }
        }
        // next iteration's first __syncthreads separates coef/frag reuse
    }
}

extern "C" void kernel_launch(void* const* d_in, const int* in_sizes, int n_in,
                              void* d_out, int out_size) {
    const float* X    = (const float*)d_in[0];
    const float* W    = (const float*)d_in[1];
    const float* bias = (const float*)d_in[2];
    float* out = (float*)d_out;

    int nrows = in_sizes[0] / DIN;

    cudaFuncSetAttribute(mobius_mma_kernel,
                         cudaFuncAttributeMaxDynamicSharedMemorySize, SMEM_TOTAL);

    int nsm = 148;
    cudaDeviceGetAttribute(&nsm, cudaDevAttrMultiProcessorCount, 0);
    int ntiles = nrows / TILE_M;
    int grid = nsm < ntiles ? nsm : ntiles;

    mobius_mma_kernel<<<grid, THREADS, SMEM_TOTAL>>>(X, W, bias, out, nrows);
}

// round 5
// speedup vs baseline: 2.2856x; 1.0997x over previous
#include <cuda_runtime.h>
#include <cstdint>

#define DIN    128
#define DOUT   128
#define TILE_M 128
#define THREADS 256

// ---- smem byte offsets ----
#define OFF_WH   0                    // W hi frags: 8s x 8pairs x 32 lanes x 16B = 32KB
#define OFF_WL   32768
#define OFF_A    65536                // per-group AH 32KB + AL 32KB
#define AH_OFF(g) (OFF_A + (g)*65536)
#define AL_OFF(g) (AH_OFF(g) + 32768)
#define OFF_BIAS 196608               // 128 f32
#define OFF_B2   (OFF_BIAS + 512)
#define OFF_GRP  (OFF_B2 + 16)
#define GRP_STRIDE 3584               // xn2 512 + rs2 1024 + rsb 1024 + cA 512 + cB 512
#define OFF_XN2(g) (OFF_GRP + (g)*GRP_STRIDE)
#define OFF_RS2(g) (OFF_XN2(g) + 512)
#define OFF_RSB(g) (OFF_RS2(g) + 1024)
#define OFF_CA(g)  (OFF_RSB(g) + 1024)
#define OFF_CB(g)  (OFF_CA(g) + 512)
#define SMEM_TOTAL (OFF_GRP + 2*GRP_STRIDE)

__device__ __forceinline__ uint32_t packbf(float hi, float lo) {
    uint32_t r; asm("cvt.rn.bf16x2.f32 %0, %1, %2;" : "=r"(r) : "f"(hi), "f"(lo)); return r;
}
__device__ __forceinline__ float lo_bf(uint32_t p) { return __uint_as_float(p << 16); }
__device__ __forceinline__ float hi_bf(uint32_t p) { return __uint_as_float(p & 0xffff0000u); }

__device__ __forceinline__ void mma_bf16(float4& d, const uint4& a, uint32_t b0, uint32_t b1) {
    asm volatile("mma.sync.aligned.m16n8k16.row.col.f32.bf16.bf16.f32 "
        "{%0,%1,%2,%3}, {%4,%5,%6,%7}, {%8,%9}, {%0,%1,%2,%3};"
        : "+f"(d.x), "+f"(d.y), "+f"(d.z), "+f"(d.w)
        : "r"(a.x), "r"(a.y), "r"(a.z), "r"(a.w), "r"(b0), "r"(b1));
}
__device__ __forceinline__ void barg(int id) {
    asm volatile("bar.sync %0, %1;" :: "r"(id), "r"(128) : "memory");
}
__device__ __forceinline__ void pf_l2(const void* p) {
    asm volatile("prefetch.global.L2 [%0];" :: "l"(p));
}

extern "C" __global__ void __launch_bounds__(THREADS, 1)
mobius_mma2_kernel(const float* __restrict__ X,
                   const float* __restrict__ W,
                   const float* __restrict__ bias,
                   float* __restrict__ out,
                   int nrows)
{
    extern __shared__ __align__(16) char smem[];
    float* sbias = (float*)(smem + OFF_BIAS);
    float* sB2   = (float*)(smem + OFF_B2);

    const int tid  = threadIdx.x;
    const int lane = tid & 31;
    const int wid  = tid >> 5;
    const int g    = lane >> 2;
    const int cg   = lane & 3;
    const int gid  = tid >> 7;        // group 0/1 (128 threads each)
    const int wg   = wid & 3;         // warp within group
    const int wm2  = wg >> 1;         // m-half of warp tile
    const int wn2  = wg & 1;          // n-half of warp tile
    const int barid = gid + 1;

    if (tid < 128) sbias[tid] = bias[tid];

    // ---- W conversion (once, all 256 threads): warp wid = k-step s ----
    {
        const float* wp0 = W + wid * 16 + 2 * cg;
        #pragma unroll
        for (int nt = 0; nt < 16; nt++) {
            int n = nt * 8 + g;
            const float* wp = wp0 + n * DIN;
            float2 u0 = *(const float2*)(wp);
            float2 u1 = *(const float2*)(wp + 8);
            uint32_t h0 = packbf(u0.y, u0.x);
            uint32_t h1 = packbf(u1.y, u1.x);
            uint32_t l0 = packbf(u0.y - hi_bf(h0), u0.x - lo_bf(h0));
            uint32_t l1 = packbf(u1.y - hi_bf(h1), u1.x - lo_bf(h1));
            int p = nt >> 1, half = nt & 1;
            int off = ((wid * 8 + p) * 32 + lane) * 16 + half * 8;
            uint2 vh; vh.x = h0; vh.y = h1;
            uint2 vl; vl.x = l0; vl.y = l1;
            *(uint2*)(smem + OFF_WH + off) = vh;
            *(uint2*)(smem + OFF_WL + off) = vl;
        }
    }
    __syncthreads();
    if (tid < 32) {
        float s = 0.f;
        #pragma unroll
        for (int i = 0; i < 4; i++) { float v = sbias[tid + 32 * i]; s = fmaf(v, v, s); }
        #pragma unroll
        for (int o = 16; o; o >>= 1) s += __shfl_xor_sync(0xffffffffu, s, o);
        if (tid == 0) *sB2 = s;
    }
    __syncthreads();   // last CTA-wide barrier; groups diverge after this

    char* AHp = smem + AH_OFF(gid);
    char* ALp = smem + AL_OFF(gid);
    float* xn2g = (float*)(smem + OFF_XN2(gid));
    float* rs2g = (float*)(smem + OFF_RS2(gid));
    float* rsbg = (float*)(smem + OFF_RSB(gid));
    float* cAg  = (float*)(smem + OFF_CA(gid));
    float* cBg  = (float*)(smem + OFF_CB(gid));

    const int ntiles = nrows / TILE_M;
    const int gstep  = gridDim.x * 2;
    const int tstart = blockIdx.x * 2 + gid;

    for (int t = tstart; t < ntiles; t += gstep) {
        const long long rowbase = (long long)t * TILE_M;

        // ---- A conversion: warp wg -> frag rows {2wg, 2wg+1}; global -> frags ----
        float xs[4] = {0.f, 0.f, 0.f, 0.f};
        #pragma unroll
        for (int i2 = 0; i2 < 2; i2++) {
            int ifr = wg * 2 + i2;
            const float* b0p = X + (rowbase + ifr * 16 + g) * DIN + 2 * cg;
            const float* b1p = b0p + 8 * DIN;
            #pragma unroll
            for (int s = 0; s < 8; s++) {
                float2 v00 = *(const float2*)(b0p + 16 * s);
                float2 v01 = *(const float2*)(b0p + 16 * s + 8);
                float2 v10 = *(const float2*)(b1p + 16 * s);
                float2 v11 = *(const float2*)(b1p + 16 * s + 8);
                xs[i2*2+0] = fmaf(v00.x, v00.x, xs[i2*2+0]);
                xs[i2*2+0] = fmaf(v00.y, v00.y, xs[i2*2+0]);
                xs[i2*2+0] = fmaf(v01.x, v01.x, xs[i2*2+0]);
                xs[i2*2+0] = fmaf(v01.y, v01.y, xs[i2*2+0]);
                xs[i2*2+1] = fmaf(v10.x, v10.x, xs[i2*2+1]);
                xs[i2*2+1] = fmaf(v10.y, v10.y, xs[i2*2+1]);
                xs[i2*2+1] = fmaf(v11.x, v11.x, xs[i2*2+1]);
                xs[i2*2+1] = fmaf(v11.y, v11.y, xs[i2*2+1]);
                uint4 h, l;
                h.x = packbf(v00.y, v00.x);
                h.y = packbf(v10.y, v10.x);
                h.z = packbf(v01.y, v01.x);
                h.w = packbf(v11.y, v11.x);
                l.x = packbf(v00.y - hi_bf(h.x), v00.x - lo_bf(h.x));
                l.y = packbf(v10.y - hi_bf(h.y), v10.x - lo_bf(h.y));
                l.z = packbf(v01.y - hi_bf(h.z), v01.x - lo_bf(h.z));
                l.w = packbf(v11.y - hi_bf(h.w), v11.x - lo_bf(h.w));
                int off = ((ifr * 8 + s) * 32 + lane) * 16;
                *(uint4*)(AHp + off) = h;
                *(uint4*)(ALp + off) = l;
            }
        }
        #pragma unroll
        for (int q = 0; q < 4; q++) {
            xs[q] += __shfl_xor_sync(0xffffffffu, xs[q], 1);
            xs[q] += __shfl_xor_sync(0xffffffffu, xs[q], 2);
        }
        if (cg == 0) {
            xn2g[(wg * 2) * 16 + g]           = xs[0];
            xn2g[(wg * 2) * 16 + g + 8]       = xs[1];
            xn2g[(wg * 2 + 1) * 16 + g]       = xs[2];
            xn2g[(wg * 2 + 1) * 16 + g + 8]   = xs[3];
        }

        // ---- L2 prefetch for this group's next tile ----
        {
            int tn = t + gstep;
            if (tn < ntiles) {
                const char* pf = (const char*)(X + (long long)tn * TILE_M * DIN)
                               + (long long)(tid & 127) * 512;
                pf_l2(pf); pf_l2(pf + 128); pf_l2(pf + 256); pf_l2(pf + 384);
            }
        }

        barg(barid);   // frags + xn2 visible to group

        // ---- mainloop: warp tile m64 x n64, 3-pass bf16 ----
        float4 acc[4][8];
        #pragma unroll
        for (int i = 0; i < 4; i++)
            #pragma unroll
            for (int j = 0; j < 8; j++) acc[i][j] = make_float4(0.f, 0.f, 0.f, 0.f);

        #pragma unroll
        for (int s = 0; s < 8; s++) {
            uint4 ah[4], wh4[4];
            #pragma unroll
            for (int i = 0; i < 4; i++)
                ah[i] = *(const uint4*)(AHp + ((((wm2 * 4 + i) * 8 + s) * 32 + lane) * 16));
            #pragma unroll
            for (int u = 0; u < 4; u++)
                wh4[u] = *(const uint4*)(smem + OFF_WH + (((s * 8 + wn2 * 4 + u) * 32 + lane) * 16));
            #pragma unroll
            for (int i = 0; i < 4; i++)
                #pragma unroll
                for (int u = 0; u < 4; u++) {
                    mma_bf16(acc[i][2*u],   ah[i], wh4[u].x, wh4[u].y);
                    mma_bf16(acc[i][2*u+1], ah[i], wh4[u].z, wh4[u].w);
                }
            uint4 al[4];
            #pragma unroll
            for (int i = 0; i < 4; i++)
                al[i] = *(const uint4*)(ALp + ((((wm2 * 4 + i) * 8 + s) * 32 + lane) * 16));
            #pragma unroll
            for (int i = 0; i < 4; i++)
                #pragma unroll
                for (int u = 0; u < 4; u++) {
                    mma_bf16(acc[i][2*u],   al[i], wh4[u].x, wh4[u].y);
                    mma_bf16(acc[i][2*u+1], al[i], wh4[u].z, wh4[u].w);
                }
            uint4 wl4[4];
            #pragma unroll
            for (int u = 0; u < 4; u++)
                wl4[u] = *(const uint4*)(smem + OFF_WL + (((s * 8 + wn2 * 4 + u) * 32 + lane) * 16));
            #pragma unroll
            for (int i = 0; i < 4; i++)
                #pragma unroll
                for (int u = 0; u < 4; u++) {
                    mma_bf16(acc[i][2*u],   ah[i], wl4[u].x, wl4[u].y);
                    mma_bf16(acc[i][2*u+1], ah[i], wl4[u].z, wl4[u].w);
                }
        }

        // ---- epilogue reductions: ||Mx||^2 and <Mx,bias> per row ----
        float2 bj[8];
        #pragma unroll
        for (int j = 0; j < 8; j++)
            bj[j] = *(const float2*)(sbias + wn2 * 64 + j * 8 + 2 * cg);

        #pragma unroll
        for (int i = 0; i < 4; i++) {
            float s2r0 = 0.f, s2r1 = 0.f, sbr0 = 0.f, sbr1 = 0.f;
            #pragma unroll
            for (int j = 0; j < 8; j++) {
                float4 d = acc[i][j];
                s2r0 = fmaf(d.x, d.x, s2r0); s2r0 = fmaf(d.y, d.y, s2r0);
                s2r1 = fmaf(d.z, d.z, s2r1); s2r1 = fmaf(d.w, d.w, s2r1);
                sbr0 = fmaf(d.x, bj[j].x, sbr0); sbr0 = fmaf(d.y, bj[j].y, sbr0);
                sbr1 = fmaf(d.z, bj[j].x, sbr1); sbr1 = fmaf(d.w, bj[j].y, sbr1);
            }
            s2r0 += __shfl_xor_sync(0xffffffffu, s2r0, 1);
            s2r0 += __shfl_xor_sync(0xffffffffu, s2r0, 2);
            s2r1 += __shfl_xor_sync(0xffffffffu, s2r1, 1);
            s2r1 += __shfl_xor_sync(0xffffffffu, s2r1, 2);
            sbr0 += __shfl_xor_sync(0xffffffffu, sbr0, 1);
            sbr0 += __shfl_xor_sync(0xffffffffu, sbr0, 2);
            sbr1 += __shfl_xor_sync(0xffffffffu, sbr1, 1);
            sbr1 += __shfl_xor_sync(0xffffffffu, sbr1, 2);
            if (cg == 0) {
                int r0 = wm2 * 64 + i * 16 + g;
                rs2g[2 * r0 + wn2]       = s2r0;
                rs2g[2 * (r0 + 8) + wn2] = s2r1;
                rsbg[2 * r0 + wn2]       = sbr0;
                rsbg[2 * (r0 + 8) + wn2] = sbr1;
            }
        }
        barg(barid);   // reductions visible; mainloop done (frags free next iter)

        // ---- per-row scalar math -> coefficients ----
        {
            int r = tid & 127;
            float mxn2 = rs2g[2 * r] + rs2g[2 * r + 1];
            float dotb = rsbg[2 * r] + rsbg[2 * r + 1];
            float b2c = *sB2;
            float xn  = fmaxf(sqrtf(xn2g[r]), 1e-15f);
            float mxn = fmaxf(sqrtf(mxn2),    1e-15f);
            float u   = fminf(xn, 1.0f - 1e-7f);
            float at  = 0.5f * (log1pf(u) - log1pf(-u));
            float sc  = tanhf(mxn / xn * at) / mxn;
            if (mxn <= 1e-10f) sc = 0.0f;
            float xy    = sc * dotb;
            float y2    = sc * sc * mxn2;
            float alpha = 1.0f + 2.0f * xy + b2c;
            float beta  = 1.0f - y2;
            float den   = fmaxf(1.0f + 2.0f * xy + y2 * b2c, 1e-15f);
            float A  = sc * alpha / den;
            float Bc = beta / den;
            float o2 = A * A * mxn2 + 2.0f * A * Bc * dotb + Bc * Bc * b2c;
            float on = fmaxf(sqrtf(o2), 1e-15f);
            float mxv = 1.0f - 1e-5f;
            float fpr = (on > mxv) ? (mxv / on) : 1.0f;
            cAg[r] = A * fpr;
            cBg[r] = Bc * fpr;
        }
        barg(barid);   // coefs ready

        // ---- stores: out = A[r]*Mx + B[r]*bias straight from regs ----
        {
            float* obase = out + rowbase * DOUT + wn2 * 64 + 2 * cg;
            #pragma unroll
            for (int i = 0; i < 4; i++) {
                int r0 = wm2 * 64 + i * 16 + g;
                float A0 = cAg[r0],     B0 = cBg[r0];
                float A1 = cAg[r0 + 8], B1 = cBg[r0 + 8];
                float* op0 = obase + (long long)r0 * DOUT;
                float* op1 = op0 + 8 * DOUT;
                #pragma unroll
                for (int j = 0; j < 8; j++) {
                    float4 d = acc[i][j];
                    float2 o0, o1;
                    o0.x = fmaf(A0, d.x, B0 * bj[j].x);
                    o0.y = fmaf(A0, d.y, B0 * bj[j].y);
                    o1.x = fmaf(A1, d.z, B1 * bj[j].x);
                    o1.y = fmaf(A1, d.w, B1 * bj[j].y);
                    *(float2*)(op0 + j * 8) = o0;
                    *(float2*)(op1 + j * 8) = o1;
                }
            }
        }
        // next iter: conversion (after this group's warps pass the two bars above)
    }
}

extern "C" void kernel_launch(void* const* d_in, const int* in_sizes, int n_in,
                              void* d_out, int out_size) {
    const float* X    = (const float*)d_in[0];
    const float* W    = (const float*)d_in[1];
    const float* bias = (const float*)d_in[2];
    float* out = (float*)d_out;

    int nrows = in_sizes[0] / DIN;

    cudaFuncSetAttribute(mobius_mma2_kernel,
                         cudaFuncAttributeMaxDynamicSharedMemorySize, SMEM_TOTAL);

    int nsm = 148;
    cudaDeviceGetAttribute(&nsm, cudaDevAttrMultiProcessorCount, 0);
    int ntiles = nrows / TILE_M;
    int grid = nsm;
    if (grid * 2 > ntiles) grid = (ntiles + 1) / 2;

    mobius_mma2_kernel<<<grid, THREADS, SMEM_TOTAL>>>(X, W, bias, out, nrows);
}